// round 11
// baseline (speedup 1.0000x reference)
#include <cuda_runtime.h>
#include <cstddef>

// Problem constants
#define NB   16
#define NT   64
#define NF0  8
#define NN   100
#define BT   (NB * NT)            // 1024
#define ROWSTRIDE (NF0 * NN)      // 800 floats per (b,t) slice
#define SLAB ((size_t)BT * ROWSTRIDE)  // 819200 floats per k-slab

__device__ float g_z[15 * BT * ROWSTRIDE];   // slabs k=1..15 (~49 MB)

// ---- packed f32x2 helpers ----
typedef unsigned long long ull;
__device__ __forceinline__ ull pack2(float lo, float hi) {
    ull r; asm("mov.b64 %0, {%1,%2};" : "=l"(r) : "f"(lo), "f"(hi)); return r;
}
__device__ __forceinline__ void unpack2(ull v, float& lo, float& hi) {
    asm("mov.b64 {%0,%1}, %2;" : "=f"(lo), "=f"(hi) : "l"(v));
}
__device__ __forceinline__ ull ffma2(ull a, ull b, ull c) {
    ull d; asm("fma.rn.f32x2 %0, %1, %2, %3;" : "=l"(d) : "l"(a), "l"(b), "l"(c));
    return d;
}

// ---------------------------------------------------------------------------
// Diffusion step k (R9 version — measured best, keep as control):
// thread = output column m (tid<100), owns all 8 f accumulators (4 x f32x2).
// ---------------------------------------------------------------------------
__global__ __launch_bounds__(128)
void diffuse_step_kernel(const float* __restrict__ x,
                         const float* __restrict__ S,
                         int k)
{
    int bt  = blockIdx.x;
    int t   = bt & 63;
    if (t < k) return;
    int tid = threadIdx.x;

    const float* src = (k == 1)
        ? (x + (size_t)(bt - 1) * ROWSTRIDE)
        : (g_z + (size_t)(k - 2) * SLAB + (size_t)(bt - 1) * ROWSTRIDE);

    __shared__ float At[NN * NF0];            // [n][f]
    for (int i = tid; i < ROWSTRIDE; i += 128) {
        int f = i / NN, n = i % NN;
        At[n * 8 + f] = src[i];
    }
    __syncthreads();

    if (tid < 100) {
        int m = tid;
        const float* Sp = S + (size_t)bt * (NN * NN) + m;

        ull acc01 = 0ull, acc23 = 0ull, acc45 = 0ull, acc67 = 0ull;
        #pragma unroll 4
        for (int n = 0; n < NN; n++) {
            float s = Sp[(size_t)n * NN];
            ull s2 = pack2(s, s);
            const ull* ar = reinterpret_cast<const ull*>(At + n * 8);
            acc01 = ffma2(ar[0], s2, acc01);
            acc23 = ffma2(ar[1], s2, acc23);
            acc45 = ffma2(ar[2], s2, acc45);
            acc67 = ffma2(ar[3], s2, acc67);
        }
        float* dst = g_z + (size_t)(k - 1) * SLAB + (size_t)bt * ROWSTRIDE + m;
        float v0, v1;
        unpack2(acc01, v0, v1); dst[0 * NN] = v0; dst[1 * NN] = v1;
        unpack2(acc23, v0, v1); dst[2 * NN] = v0; dst[3 * NN] = v1;
        unpack2(acc45, v0, v1); dst[4 * NN] = v0; dst[5 * NN] = v1;
        unpack2(acc67, v0, v1); dst[6 * NN] = v0; dst[7 * NN] = v1;
    }
}

// ---------------------------------------------------------------------------
// Fused head v3, ROW-PAIR PACKED, ALL STAGES 256 THREADS.
// Activations stored as float2 of (row 2rp, row 2rp+1); packed FMA2 operands
// come straight from LDS.64; weights pre-packed (w,w), padded strides.
//
// Smem (floats):
//  [0,4096)       zp [col=f*16+k][32r]  -> reused as y2p [d][32r]
//  [4096,10240)   y1p [col=f1*6+p][32r]
//  [10240,12352)  w1p [c][33] float2
//  [12352,24768)  w2p [c][97] float2
//  [24768,24800)  b1, [24800,24864) b2
//  after conv2 (y1p/w1p/w2p dead):
//  [4096,20608)   fc1wp [j=64][129 d] ull   (16512 float-slots)
//  [20608,22720)  hsh (32 x 66)
//  [22720,22784)  fc1b, [22784,23104) fc2w, [23104,23109) fc2b
// ---------------------------------------------------------------------------
#define OFF_Y1P  4096
#define OFF_W1P  10240
#define OFF_W2P  12352
#define OFF_B1   24768
#define OFF_B2   24800
#define OFF_FC1W 4096
#define OFF_HSH  20608
#define HS       66
#define OFF_FC1B 22720
#define OFF_FC2W 22784
#define OFF_FC2B 23104
#define SMEM_FLOATS 24864

__global__ __launch_bounds__(256, 2)
void head_kernel(const float* __restrict__ x,
                 const float* __restrict__ w1g, const float* __restrict__ b1g,
                 const float* __restrict__ w2g, const float* __restrict__ b2g,
                 const float* __restrict__ f1wg, const float* __restrict__ f1bg,
                 const float* __restrict__ f2wg, const float* __restrict__ f2bg,
                 float* __restrict__ out)
{
    extern __shared__ float sm[];
    ull*   zpu  = reinterpret_cast<ull*>(sm);            // zp / y2p packed
    ull*   y1pu = reinterpret_cast<ull*>(sm + OFF_Y1P);
    float* hsh  = sm + OFF_HSH;
    const ull* w1pu = reinterpret_cast<const ull*>(sm + OFF_W1P);
    const ull* w2pu = reinterpret_cast<const ull*>(sm + OFF_W2P);
    float* b1sh = sm + OFF_B1;
    float* b2sh = sm + OFF_B2;

    int tid  = threadIdx.x;
    int row0 = blockIdx.x * 32;

    // ---- stage 0: gather z -> [col][r] layout + pack conv weights ----
    for (int i = tid; i < 4096; i += 256) {
        int r  = i & 31;
        int kf = i >> 5;
        int f  = kf >> 4;
        int k  = kf & 15;
        int R  = row0 + r;
        int n  = R % NN;
        int bt = R / NN;
        float v;
        if (k == 0) {
            v = x[(size_t)bt * ROWSTRIDE + f * NN + n];
        } else if ((bt & 63) < k) {
            v = 0.f;
        } else {
            v = g_z[(size_t)(k - 1) * SLAB + (size_t)bt * ROWSTRIDE + f * NN + n];
        }
        sm[(f * 16 + k) * 32 + r] = v;
    }
    {
        ull* w1w = reinterpret_cast<ull*>(sm + OFF_W1P);
        for (int i = tid; i < 1024; i += 256) {
            int c = i >> 5, rmn = i & 31;
            float v = w1g[i];
            w1w[c * 33 + rmn] = pack2(v, v);
        }
        ull* w2w = reinterpret_cast<ull*>(sm + OFF_W2P);
        for (int i = tid; i < 6144; i += 256) {
            int c = i / 96, rmn = i % 96;
            float v = w2g[i];
            w2w[c * 97 + rmn] = pack2(v, v);
        }
        if (tid < 32) b1sh[tid] = b1g[tid];
        if (tid < 64) b2sh[tid] = b2g[tid];
    }
    __syncthreads();

    // ---- conv1 + relu + pool2 : (rp, fg in [0,16)), 2 channels each ----
    {
        int rp = tid & 15, fg = tid >> 4;
        ull acc2[2][12];
        #pragma unroll
        for (int c = 0; c < 2; c++)
            #pragma unroll
            for (int p = 0; p < 12; p++) acc2[c][p] = 0ull;

        #pragma unroll 2
        for (int f0 = 0; f0 < 8; f0++) {
            ull ap[16];
            #pragma unroll
            for (int i = 0; i < 16; i++) ap[i] = zpu[(f0 * 16 + i) * 16 + rp];
            #pragma unroll
            for (int c = 0; c < 2; c++) {
                int ch = fg * 2 + c;
                #pragma unroll
                for (int kk = 0; kk < 4; kk++) {
                    ull w = w1pu[ch * 33 + f0 * 4 + kk];
                    #pragma unroll
                    for (int p = 0; p < 12; p++)
                        acc2[c][p] = ffma2(ap[p + kk], w, acc2[c][p]);
                }
            }
        }
        #pragma unroll
        for (int c = 0; c < 2; c++) {
            int f1 = fg * 2 + c;
            float bb = b1sh[f1];
            #pragma unroll
            for (int pp = 0; pp < 6; pp++) {
                float alo, ahi, blo, bhi;
                unpack2(acc2[c][2 * pp],     alo, ahi);
                unpack2(acc2[c][2 * pp + 1], blo, bhi);
                float lo = fmaxf(fmaxf(alo + bb, 0.f), fmaxf(blo + bb, 0.f));
                float hi = fmaxf(fmaxf(ahi + bb, 0.f), fmaxf(bhi + bb, 0.f));
                y1pu[(f1 * 6 + pp) * 16 + rp] = pack2(lo, hi);
            }
        }
    }
    __syncthreads();

    // ---- conv2 + relu + pool2 : (rp, cg in [0,16)), 4 channels each ----
    {
        int rp = tid & 15, cg = tid >> 4;
        int c0 = cg * 4;
        ull acc2[4][4];
        #pragma unroll
        for (int c = 0; c < 4; c++)
            #pragma unroll
            for (int p = 0; p < 4; p++) acc2[c][p] = 0ull;

        #pragma unroll 4
        for (int f1 = 0; f1 < 32; f1++) {
            ull ap[6];
            #pragma unroll
            for (int i = 0; i < 6; i++) ap[i] = y1pu[(f1 * 6 + i) * 16 + rp];
            #pragma unroll
            for (int c = 0; c < 4; c++) {
                const ull* wb = w2pu + (c0 + c) * 97 + f1 * 3;
                ull w0 = wb[0], w1 = wb[1], w2 = wb[2];
                #pragma unroll
                for (int p = 0; p < 4; p++) {
                    acc2[c][p] = ffma2(ap[p],     w0, acc2[c][p]);
                    acc2[c][p] = ffma2(ap[p + 1], w1, acc2[c][p]);
                    acc2[c][p] = ffma2(ap[p + 2], w2, acc2[c][p]);
                }
            }
        }
        #pragma unroll
        for (int c = 0; c < 4; c++) {
            int f2 = c0 + c;
            float bb = b2sh[f2];
            float u0l,u0h,u1l,u1h,u2l,u2h,u3l,u3h;
            unpack2(acc2[c][0], u0l, u0h);
            unpack2(acc2[c][1], u1l, u1h);
            unpack2(acc2[c][2], u2l, u2h);
            unpack2(acc2[c][3], u3l, u3h);
            float v0l = fmaxf(fmaxf(u0l + bb, 0.f), fmaxf(u1l + bb, 0.f));
            float v0h = fmaxf(fmaxf(u0h + bb, 0.f), fmaxf(u1h + bb, 0.f));
            float v1l = fmaxf(fmaxf(u2l + bb, 0.f), fmaxf(u3l + bb, 0.f));
            float v1h = fmaxf(fmaxf(u2h + bb, 0.f), fmaxf(u3h + bb, 0.f));
            zpu[(f2 * 2 + 0) * 16 + rp] = pack2(v0l, v0h);   // y2p (zp reused)
            zpu[(f2 * 2 + 1) * 16 + rp] = pack2(v1l, v1h);
        }
    }
    __syncthreads();                             // y1p/w1p/w2p now dead

    // ---- stage fc weights (packed) into dead region ----
    {
        ull* fc1wp = reinterpret_cast<ull*>(sm + OFF_FC1W);  // [j*129 + d]
        for (int i = tid; i < 8192; i += 256) {
            int d = i & 127;
            int j = i >> 7;
            float v = f1wg[i];                   // coalesced over d
            fc1wp[j * 129 + d] = pack2(v, v);
        }
        if (tid < 64) sm[OFF_FC1B + tid] = f1bg[tid];
        if (tid < 5)  sm[OFF_FC2B + tid] = f2bg[tid];
        for (int i = tid; i < 320; i += 256) sm[OFF_FC2W + i] = f2wg[i];
    }
    __syncthreads();

    // ---- fc1 + relu : 256 threads = (rp, hg in [0,16)), 2 rows x 4 hidden ----
    {
        const ull* fc1wp = reinterpret_cast<const ull*>(sm + OFF_FC1W);
        const float* fb  = sm + OFF_FC1B;
        int rp = tid & 15, hg = tid >> 4;
        ull acc2[4];
        acc2[0] = acc2[1] = acc2[2] = acc2[3] = 0ull;

        #pragma unroll 4
        for (int d = 0; d < 128; d++) {
            ull ap = zpu[d * 16 + rp];           // y2p packed rows
            acc2[0] = ffma2(ap, fc1wp[(hg * 4 + 0) * 129 + d], acc2[0]);
            acc2[1] = ffma2(ap, fc1wp[(hg * 4 + 1) * 129 + d], acc2[1]);
            acc2[2] = ffma2(ap, fc1wp[(hg * 4 + 2) * 129 + d], acc2[2]);
            acc2[3] = ffma2(ap, fc1wp[(hg * 4 + 3) * 129 + d], acc2[3]);
        }
        #pragma unroll
        for (int j = 0; j < 4; j++) {
            float lo, hi; unpack2(acc2[j], lo, hi);
            float bb = fb[hg * 4 + j];
            hsh[(2 * rp)     * HS + hg * 4 + j] = fmaxf(lo + bb, 0.f);
            hsh[(2 * rp + 1) * HS + hg * 4 + j] = fmaxf(hi + bb, 0.f);
        }
    }
    __syncthreads();

    // ---- fc2 (packed dot) + transposed output write: out[b,t,o,n] ----
    if (tid < 160) {
        const ull* fc2wp = reinterpret_cast<const ull*>(sm + OFF_FC2W);
        const float* fc2b = sm + OFF_FC2B;
        int r = tid & 31, o = tid >> 5;
        const ull* hp = reinterpret_cast<const ull*>(hsh + r * HS);
        const ull* wp = fc2wp + o * 32;
        ull acc2 = 0ull;
        #pragma unroll 8
        for (int jp = 0; jp < 32; jp++)
            acc2 = ffma2(hp[jp], wp[jp], acc2);
        float lo, hi; unpack2(acc2, lo, hi);
        float acc = lo + hi + fc2b[o];
        int R  = row0 + r;
        int n  = R % NN;
        int bt = R / NN;
        out[((size_t)bt * 5 + o) * NN + n] = acc;
    }
}

// ---------------------------------------------------------------------------
extern "C" void kernel_launch(void* const* d_in, const int* in_sizes, int n_in,
                              void* d_out, int out_size)
{
    const float* x   = (const float*)d_in[0];
    const float* S   = (const float*)d_in[1];
    const float* w1  = (const float*)d_in[2];
    const float* b1  = (const float*)d_in[3];
    const float* w2  = (const float*)d_in[4];
    const float* b2  = (const float*)d_in[5];
    const float* f1w = (const float*)d_in[6];
    const float* f1b = (const float*)d_in[7];
    const float* f2w = (const float*)d_in[8];
    const float* f2b = (const float*)d_in[9];
    float* out = (float*)d_out;

    for (int k = 1; k <= 15; k++)
        diffuse_step_kernel<<<BT, 128>>>(x, S, k);

    size_t smem = (size_t)SMEM_FLOATS * sizeof(float);
    cudaFuncSetAttribute(head_kernel,
                         cudaFuncAttributeMaxDynamicSharedMemorySize, (int)smem);
    head_kernel<<<(NB * NT * NN) / 32, 256, smem>>>(
        x, w1, b1, w2, b2, f1w, f1b, f2w, f2b, out);
}